// round 7
// baseline (speedup 1.0000x reference)
#include <cuda_runtime.h>

// ---------------------------------------------------------------------------
// RMSPELoss: per-row permutation-invariant RMSE between logits[:, :4] (DoA
// estimates, radians) and the angles of the 4 one-hot label positions.
//
//   inputs  : d_in[0] = logits  float32 [131072, 181]
//             d_in[1] = labels  int32   [131072, 181]  (exactly 4 ones/row)
//   output  : d_out[0] = mean over rows of sqrt(min_perm total / 4)
//
// Memory-bound: must scan all 95 MB of labels. Strategy: warp-per-row with
// coalesced 32-lane chunks + ballot to locate the ones; 24 lanes evaluate the
// 24 permutations in parallel; deterministic two-stage reduction (no float
// atomics) so graph replays are bit-stable.
// ---------------------------------------------------------------------------

#define FULLMASK 0xFFFFFFFFu

constexpr int   BATCH    = 131072;
constexpr int   NC       = 181;
constexpr int   NBLOCK   = 2048;
constexpr int   NTHREAD  = 256;
constexpr int   WARPS_PB = NTHREAD / 32;

constexpr float PI_F       = 3.14159265358979323846f;
constexpr float TWO_PI_F   = 6.283185307179586f;
constexpr float INV_2PI_F  = 0.15915494309189535f;   // 1/(2*pi)
constexpr float DEG2RAD_F  = 0.017453292519943295f;  // pi/180

// All 24 permutations of {0,1,2,3}, packed p0 | p1<<8 | p2<<16 | p3<<24.
__constant__ unsigned c_perms[24] = {
    0x03020100u, 0x02030100u, 0x03010200u, 0x01030200u, 0x02010300u, 0x01020300u,
    0x03020001u, 0x02030001u, 0x03000201u, 0x00030201u, 0x02000301u, 0x00020301u,
    0x03010002u, 0x01030002u, 0x03000102u, 0x00030102u, 0x01000302u, 0x00010302u,
    0x02010003u, 0x01020003u, 0x02000103u, 0x00020103u, 0x01000203u, 0x00010203u
};

// Per-block partial sums (static scratch — no allocation allowed).
__device__ float g_partials[NBLOCK];

// wrap (a-b) into [-pi, pi) exactly like jnp.mod(a-b+pi, 2pi) - pi, squared.
__device__ __forceinline__ float sqwrap(float a, float b) {
    float x = a - b + PI_F;
    float q = floorf(x * INV_2PI_F);
    float d = fmaf(-q, TWO_PI_F, x) - PI_F;
    return d * d;
}

__global__ __launch_bounds__(NTHREAD)
void rmspe_main(const float* __restrict__ logits, const int* __restrict__ labels)
{
    __shared__ float s_ws[WARPS_PB];

    const int lane = threadIdx.x & 31;
    const int wib  = threadIdx.x >> 5;
    const int gw   = (blockIdx.x * NTHREAD + threadIdx.x) >> 5;
    const int nw   = (NBLOCK * NTHREAD) >> 5;

    float wsum = 0.0f;

    for (int r = gw; r < BATCH; r += nw) {
        const int* lrow = labels + (long)r * NC;

        // ---- front-batched independent loads (MLP) ----
        int v0 = lrow[lane];
        int v1 = lrow[32  + lane];
        int v2 = lrow[64  + lane];
        int v3 = lrow[96  + lane];
        int v4 = lrow[128 + lane];
        int v5 = (160 + lane < NC) ? lrow[160 + lane] : 0;
        float myl = (lane < 4) ? logits[(long)r * NC + lane] : 0.0f;

        // ---- locate the 4 ones (ascending), pack 8 bits each ----
        unsigned acc = 0u;
        unsigned m;
        m = __ballot_sync(FULLMASK, v0 == 1);
        while (m) { acc = (acc << 8) | (unsigned)(__ffs(m) - 1);        m &= m - 1; }
        m = __ballot_sync(FULLMASK, v1 == 1);
        while (m) { acc = (acc << 8) | (unsigned)(32  + __ffs(m) - 1);  m &= m - 1; }
        m = __ballot_sync(FULLMASK, v2 == 1);
        while (m) { acc = (acc << 8) | (unsigned)(64  + __ffs(m) - 1);  m &= m - 1; }
        m = __ballot_sync(FULLMASK, v3 == 1);
        while (m) { acc = (acc << 8) | (unsigned)(96  + __ffs(m) - 1);  m &= m - 1; }
        m = __ballot_sync(FULLMASK, v4 == 1);
        while (m) { acc = (acc << 8) | (unsigned)(128 + __ffs(m) - 1);  m &= m - 1; }
        m = __ballot_sync(FULLMASK, v5 == 1);
        while (m) { acc = (acc << 8) | (unsigned)(160 + __ffs(m) - 1);  m &= m - 1; }

        // exactly 4 ones per row: p0..p3 ascending
        const int p0 = (acc >> 24) & 0xFF;
        const int p1 = (acc >> 16) & 0xFF;
        const int p2 = (acc >>  8) & 0xFF;
        const int p3 =  acc        & 0xFF;

        const float ang0 = ((float)p0 - 90.0f) * DEG2RAD_F;
        const float ang1 = ((float)p1 - 90.0f) * DEG2RAD_F;
        const float ang2 = ((float)p2 - 90.0f) * DEG2RAD_F;
        const float ang3 = ((float)p3 - 90.0f) * DEG2RAD_F;

        const float d0 = __shfl_sync(FULLMASK, myl, 0);
        const float d1 = __shfl_sync(FULLMASK, myl, 1);
        const float d2 = __shfl_sync(FULLMASK, myl, 2);
        const float d3 = __shfl_sync(FULLMASK, myl, 3);

        // ---- lanes 0..23: one permutation each ----
        float total = 3.4e38f;
        if (lane < 24) {
            const unsigned pm = c_perms[lane];
            float t = 0.0f;
            #pragma unroll
            for (int i = 0; i < 4; i++) {
                const int p = (pm >> (8 * i)) & 3;
                const float a = (p & 2) ? ((p & 1) ? ang3 : ang2)
                                        : ((p & 1) ? ang1 : ang0);
                const float di = (i == 0) ? d0 : (i == 1) ? d1 : (i == 2) ? d2 : d3;
                t += sqwrap(di, a);
            }
            total = t;
        }
        // warp min (all lanes converge on the min)
        #pragma unroll
        for (int off = 16; off; off >>= 1)
            total = fminf(total, __shfl_xor_sync(FULLMASK, total, off));

        if (lane == 0)
            wsum += sqrtf(total * 0.25f);
    }

    // block reduce (deterministic: fixed tree per block)
    if (lane == 0) s_ws[wib] = wsum;
    __syncthreads();
    if (threadIdx.x == 0) {
        float b = 0.0f;
        #pragma unroll
        for (int i = 0; i < WARPS_PB; i++) b += s_ws[i];
        g_partials[blockIdx.x] = b;
    }
}

__global__ __launch_bounds__(256)
void rmspe_finish(float* __restrict__ out, int out_size)
{
    __shared__ float s[256];
    float t = 0.0f;
    for (int i = threadIdx.x; i < NBLOCK; i += 256)
        t += g_partials[i];
    s[threadIdx.x] = t;
    __syncthreads();
    #pragma unroll
    for (int o = 128; o; o >>= 1) {
        if (threadIdx.x < o) s[threadIdx.x] += s[threadIdx.x + o];
        __syncthreads();
    }
    // zero any extra output elements (d_out is poisoned), then write the mean
    for (int i = 1 + threadIdx.x; i < out_size; i += 256)
        out[i] = 0.0f;
    if (threadIdx.x == 0)
        out[0] = s[0] * (1.0f / (float)BATCH);
}

extern "C" void kernel_launch(void* const* d_in, const int* in_sizes, int n_in,
                              void* d_out, int out_size)
{
    const float* logits = (const float*)d_in[0];
    const int*   labels = (const int*)d_in[1];
    (void)in_sizes; (void)n_in;

    rmspe_main<<<NBLOCK, NTHREAD>>>(logits, labels);
    rmspe_finish<<<1, 256>>>((float*)d_out, out_size);
}

// round 9
// speedup vs baseline: 1.0164x; 1.0164x over previous
#include <cuda_runtime.h>

// ---------------------------------------------------------------------------
// RMSPELoss: per-row permutation-invariant RMSE between logits[:, :4] (DoA
// estimates, radians) and the angles of the 4 one-hot label positions.
//
//   inputs  : d_in[0] = logits  float32 [131072, 181]
//             d_in[1] = labels  int32   [131072, 181]  (exactly 4 ones/row)
//   output  : mean over rows of sqrt(min_perm total / 4)
//
// R7: single fused kernel (last-block finishes the reduction; counter
// self-resets so graph replays are deterministic), single-wave persistent
// grid (148 SMs x 8 blocks), two rows in flight per warp for 2x MLP,
// streaming (.cs) loads on the zero-reuse label scan.
// ---------------------------------------------------------------------------

#define FULLMASK 0xFFFFFFFFu

constexpr int   BATCH    = 131072;
constexpr int   NC       = 181;
constexpr int   NBLOCK   = 148 * 8;        // one resident wave on GB300 (148 SMs)
constexpr int   NTHREAD  = 256;
constexpr int   WARPS_PB = NTHREAD / 32;

constexpr float PI_F       = 3.14159265358979323846f;
constexpr float TWO_PI_F   = 6.283185307179586f;
constexpr float INV_2PI_F  = 0.15915494309189535f;   // 1/(2*pi)
constexpr float DEG2RAD_F  = 0.017453292519943295f;  // pi/180

// All 24 permutations of {0,1,2,3}, packed p0 | p1<<8 | p2<<16 | p3<<24.
__constant__ unsigned c_perms[24] = {
    0x03020100u, 0x02030100u, 0x03010200u, 0x01030200u, 0x02010300u, 0x01020300u,
    0x03020001u, 0x02030001u, 0x03000201u, 0x00030201u, 0x02000301u, 0x00020301u,
    0x03010002u, 0x01030002u, 0x03000102u, 0x00030102u, 0x01000302u, 0x00010302u,
    0x02010003u, 0x01020003u, 0x02000103u, 0x00020103u, 0x01000203u, 0x00010203u
};

// Static scratch (no allocation allowed).
__device__ float    g_partials[NBLOCK];
__device__ unsigned g_count = 0;           // self-resets each launch

// wrap (a-b) into [-pi, pi) exactly like jnp.mod(a-b+pi, 2pi) - pi, squared.
__device__ __forceinline__ float sqwrap(float a, float b) {
    float x = a - b + PI_F;
    float q = floorf(x * INV_2PI_F);
    float d = fmaf(-q, TWO_PI_F, x) - PI_F;
    return d * d;
}

// Fold one 32-int label chunk's ballot into the packed ascending-index acc.
__device__ __forceinline__ void scan_chunk(unsigned& acc, int v, int base) {
    unsigned m = __ballot_sync(FULLMASK, v == 1);
    while (m) { acc = (acc << 8) | (unsigned)(base + __ffs(m) - 1); m &= m - 1; }
}

// Given the packed one-indices and this lane's logit (lanes 0..3 hold
// logits[row,0..3]), return sqrt(min-perm total / 4) on every lane.
__device__ __forceinline__ float row_rmse(unsigned acc, float myl, int lane) {
    const int p0 = (acc >> 24) & 0xFF;
    const int p1 = (acc >> 16) & 0xFF;
    const int p2 = (acc >>  8) & 0xFF;
    const int p3 =  acc        & 0xFF;

    const float ang0 = ((float)p0 - 90.0f) * DEG2RAD_F;
    const float ang1 = ((float)p1 - 90.0f) * DEG2RAD_F;
    const float ang2 = ((float)p2 - 90.0f) * DEG2RAD_F;
    const float ang3 = ((float)p3 - 90.0f) * DEG2RAD_F;

    const float d0 = __shfl_sync(FULLMASK, myl, 0);
    const float d1 = __shfl_sync(FULLMASK, myl, 1);
    const float d2 = __shfl_sync(FULLMASK, myl, 2);
    const float d3 = __shfl_sync(FULLMASK, myl, 3);

    float total = 3.4e38f;
    if (lane < 24) {
        const unsigned pm = c_perms[lane];
        float t = 0.0f;
        #pragma unroll
        for (int i = 0; i < 4; i++) {
            const int p = (pm >> (8 * i)) & 3;
            const float a = (p & 2) ? ((p & 1) ? ang3 : ang2)
                                    : ((p & 1) ? ang1 : ang0);
            const float di = (i == 0) ? d0 : (i == 1) ? d1 : (i == 2) ? d2 : d3;
            t += sqwrap(di, a);
        }
        total = t;
    }
    #pragma unroll
    for (int off = 16; off; off >>= 1)
        total = fminf(total, __shfl_xor_sync(FULLMASK, total, off));

    return sqrtf(total * 0.25f);
}

__global__ __launch_bounds__(NTHREAD)
void rmspe_fused(const float* __restrict__ logits, const int* __restrict__ labels,
                 float* __restrict__ out, int out_size)
{
    __shared__ float s_ws[WARPS_PB];
    __shared__ float s_red[NTHREAD];
    __shared__ int   s_last;

    const int lane = threadIdx.x & 31;
    const int wib  = threadIdx.x >> 5;
    const int gw   = (blockIdx.x * NTHREAD + threadIdx.x) >> 5;
    const int nw   = (NBLOCK * NTHREAD) >> 5;

    float wsum = 0.0f;

    // Two adjacent rows per iteration: front-batch all 14 loads for 2x MLP.
    for (int r = 2 * gw; r < BATCH; r += 2 * nw) {
        const int* la = labels + (long)r * NC;
        const int* lb = la + NC;

        int a0 = __ldcs(la + lane);
        int a1 = __ldcs(la + 32  + lane);
        int a2 = __ldcs(la + 64  + lane);
        int a3 = __ldcs(la + 96  + lane);
        int a4 = __ldcs(la + 128 + lane);
        int a5 = (160 + lane < NC) ? __ldcs(la + 160 + lane) : 0;
        int b0 = __ldcs(lb + lane);
        int b1 = __ldcs(lb + 32  + lane);
        int b2 = __ldcs(lb + 64  + lane);
        int b3 = __ldcs(lb + 96  + lane);
        int b4 = __ldcs(lb + 128 + lane);
        int b5 = (160 + lane < NC) ? __ldcs(lb + 160 + lane) : 0;
        float la_logit = (lane < 4) ? __ldcs(logits + (long)r * NC + lane) : 0.0f;
        float lb_logit = (lane < 4) ? __ldcs(logits + (long)(r + 1) * NC + lane) : 0.0f;

        unsigned accA = 0u, accB = 0u;
        scan_chunk(accA, a0,   0); scan_chunk(accA, a1,  32);
        scan_chunk(accA, a2,  64); scan_chunk(accA, a3,  96);
        scan_chunk(accA, a4, 128); scan_chunk(accA, a5, 160);
        scan_chunk(accB, b0,   0); scan_chunk(accB, b1,  32);
        scan_chunk(accB, b2,  64); scan_chunk(accB, b3,  96);
        scan_chunk(accB, b4, 128); scan_chunk(accB, b5, 160);

        const float ra = row_rmse(accA, la_logit, lane);
        const float rb = row_rmse(accB, lb_logit, lane);
        if (lane == 0) wsum += ra + rb;
    }

    // ---- block reduce (deterministic fixed tree) ----
    if (lane == 0) s_ws[wib] = wsum;
    __syncthreads();
    if (threadIdx.x == 0) {
        float b = 0.0f;
        #pragma unroll
        for (int i = 0; i < WARPS_PB; i++) b += s_ws[i];
        g_partials[blockIdx.x] = b;
        __threadfence();
        unsigned old = atomicAdd(&g_count, 1u);
        s_last = (old == NBLOCK - 1) ? 1 : 0;
    }
    __syncthreads();

    // ---- last block finishes: deterministic fixed-order tree over partials ----
    if (s_last) {
        __threadfence();
        float t = 0.0f;
        for (int i = threadIdx.x; i < NBLOCK; i += NTHREAD)
            t += __ldcg(&g_partials[i]);
        s_red[threadIdx.x] = t;
        __syncthreads();
        #pragma unroll
        for (int o = NTHREAD / 2; o; o >>= 1) {
            if (threadIdx.x < o) s_red[threadIdx.x] += s_red[threadIdx.x + o];
            __syncthreads();
        }
        // zero any extra output elements (d_out is poisoned)
        for (int i = 1 + threadIdx.x; i < out_size; i += NTHREAD)
            out[i] = 0.0f;
        if (threadIdx.x == 0) {
            out[0]  = s_red[0] * (1.0f / (float)BATCH);
            g_count = 0;                    // reset for next graph replay
        }
    }
}

extern "C" void kernel_launch(void* const* d_in, const int* in_sizes, int n_in,
                              void* d_out, int out_size)
{
    const float* logits = (const float*)d_in[0];
    const int*   labels = (const int*)d_in[1];
    (void)in_sizes; (void)n_in;

    rmspe_fused<<<NBLOCK, NTHREAD>>>(logits, labels, (float*)d_out, out_size);
}